// round 1
// baseline (speedup 1.0000x reference)
#include <cuda_runtime.h>

#define CB 32
#define CT 1024
#define CV 1024
#define CL 100
#define CS 201          // 2*L+1
#define S_PAD 224       // row stride for lp scratch (128B aligned rows)
#define NEGF (-1e30f)
#define LOG2E 1.4426950408889634f
#define LN2F  0.6931471805599453f

// Scratch: gathered extended-label log2-probs  [B][T][S_PAD]
__device__ float g_lp[(size_t)CB * CT * S_PAD];
__device__ float g_loss[CB];

// ---------------------------------------------------------------------------
// Kernel 1: per-(b,t) log-sum-exp over V, fused with gather of the 201
// extended-label log-probs (log2 domain) into g_lp.
// grid = (T, B), 256 threads, each thread holds 4 floats (float4).
// ---------------------------------------------------------------------------
__global__ void __launch_bounds__(256) lse_gather_kernel(
    const float* __restrict__ logits, const int* __restrict__ targets)
{
    const int t = blockIdx.x, b = blockIdx.y;
    const float* row = logits + ((size_t)b * CT + t) * CV;

    __shared__ float sh[CV];
    __shared__ float red[8];
    __shared__ float bc[2];

    const int tid = threadIdx.x;
    float4 v = reinterpret_cast<const float4*>(row)[tid];
    reinterpret_cast<float4*>(sh)[tid] = v;

    // block max
    float m = fmaxf(fmaxf(v.x, v.y), fmaxf(v.z, v.w));
    #pragma unroll
    for (int o = 16; o > 0; o >>= 1) m = fmaxf(m, __shfl_xor_sync(0xffffffffu, m, o));
    if ((tid & 31) == 0) red[tid >> 5] = m;
    __syncthreads();
    if (tid < 8) {
        float mm = red[tid];
        #pragma unroll
        for (int o = 4; o > 0; o >>= 1) mm = fmaxf(mm, __shfl_xor_sync(0xffu, mm, o));
        if (tid == 0) bc[0] = mm;
    }
    __syncthreads();
    m = bc[0];

    // block sum of 2^((x-m)*log2e)
    float sum = exp2f((v.x - m) * LOG2E) + exp2f((v.y - m) * LOG2E)
              + exp2f((v.z - m) * LOG2E) + exp2f((v.w - m) * LOG2E);
    #pragma unroll
    for (int o = 16; o > 0; o >>= 1) sum += __shfl_xor_sync(0xffffffffu, sum, o);
    if ((tid & 31) == 0) red[tid >> 5] = sum;
    __syncthreads();
    if (tid < 8) {
        float ss = red[tid];
        #pragma unroll
        for (int o = 4; o > 0; o >>= 1) ss += __shfl_xor_sync(0xffu, ss, o);
        if (tid == 0) bc[1] = ss;
    }
    __syncthreads();

    const float lse2 = m * LOG2E + __log2f(bc[1]);   // log2(sum_v exp(x_v)) * 1 (log2 domain)

    if (tid < CS) {
        // ext[s] = blank for even s, targets[s>>1] for odd s
        int sym = (tid & 1) ? targets[b * CL + (tid >> 1)] : (CV - 1);
        g_lp[((size_t)b * CT + t) * S_PAD + tid] = sh[sym] * LOG2E - lse2;
    }
}

// ---------------------------------------------------------------------------
// Kernel 2: CTC forward DP. One CTA per batch element, thread s = state s.
// Double-buffered alpha in SMEM (index shifted by +2 so s-1/s-2 reads never
// branch). One __syncthreads per time step. 4-deep register prefetch of lp.
// All values in log2 domain.
// ---------------------------------------------------------------------------
__global__ void __launch_bounds__(256, 1) ctc_dp_kernel(const int* __restrict__ targets)
{
    const int b = blockIdx.x;
    const int s = threadIdx.x;
    __shared__ float A[2][CS + 7];   // used indices 0 .. CS+1 (=202)

    const float* __restrict__ lpb = g_lp + (size_t)b * CT * S_PAD;
    const bool active = (s < CS);

    // allow_skip: odd s>=3 and targets[s/2] != targets[s/2 - 1]
    bool allow2 = false;
    if (s >= 3 && (s & 1)) {
        int i = s >> 1;
        allow2 = (targets[b * CL + i] != targets[b * CL + i - 1]);
    }

    // pads (never rewritten)
    if (s < 2) { A[0][s] = NEGF; A[1][s] = NEGF; }

    // alpha_0
    if (active) A[0][s + 2] = (s < 2) ? lpb[s] : NEGF;
    __syncthreads();

    // prefetch pipeline: lpr[(t-1)&3] holds lp for time t
    float lpr[4];
    #pragma unroll
    for (int i = 0; i < 4; i++)
        lpr[i] = active ? lpb[(size_t)(1 + i) * S_PAD + s] : 0.0f;

    int p = 0;
    #pragma unroll 4
    for (int t = 1; t < CT; t++) {
        const int slot = (t - 1) & 3;
        const float lp = lpr[slot];
        const int tf = t + 4;
        if (active && tf < CT) lpr[slot] = lpb[(size_t)tf * S_PAD + s];

        if (active) {
            float a  = A[p][s + 2];
            float a1 = A[p][s + 1];
            float a2 = allow2 ? A[p][s] : NEGF;
            float mx = fmaxf(a, fmaxf(a1, a2));
            float sm = exp2f(a - mx) + exp2f(a1 - mx) + exp2f(a2 - mx);
            A[p ^ 1][s + 2] = mx + __log2f(sm) + lp;
        }
        __syncthreads();
        p ^= 1;
    }

    if (s == 0) {
        float x = A[p][CS + 1];   // alpha[S-1]
        float y = A[p][CS];       // alpha[S-2]
        float mx = fmaxf(x, y);
        float l2 = mx + __log2f(exp2f(x - mx) + exp2f(y - mx));
        g_loss[b] = -l2 * LN2F;   // back to natural log
    }
}

// ---------------------------------------------------------------------------
// Kernel 3: deterministic serial mean over B.
// ---------------------------------------------------------------------------
__global__ void reduce_kernel(float* __restrict__ out)
{
    float sum = 0.0f;
    #pragma unroll
    for (int i = 0; i < CB; i++) sum += g_loss[i];
    out[0] = sum * (1.0f / CB);
}

extern "C" void kernel_launch(void* const* d_in, const int* in_sizes, int n_in,
                              void* d_out, int out_size)
{
    const int*   targets = (const int*)d_in[0];
    const float* logits  = (const float*)d_in[1];
    float*       out     = (float*)d_out;

    dim3 g1(CT, CB);
    lse_gather_kernel<<<g1, 256>>>(logits, targets);
    ctc_dp_kernel<<<CB, 256>>>(targets);
    reduce_kernel<<<1, 1>>>(out);
}

// round 3
// speedup vs baseline: 2.3658x; 2.3658x over previous
#include <cuda_runtime.h>

#define CB 32
#define CT 1024
#define CV 1024
#define CL 100
#define CS 201           // 2*L+1
#define SP 224           // 32 lanes * 7 states
#define NK 7             // states per lane
#define TMID 511         // forward computes alpha_1..alpha_511; backward B_1022..B_512
#define NEGF (-1e30f)
#define LOG2E 1.4426950408889634f
#define LN2F  0.6931471805599453f

// Scratch: gathered extended-label log2-probs, lane-permuted: [B][T][slot], slot = lane + 32*k,
// state s = 7*lane + k. Slots with s>=201 hold NEGF.
__device__ float g_lp[(size_t)CB * CT * SP];
__device__ float g_amid[CB * SP];   // alpha_{511}[s], natural s order (s>=201 -> NEGF)
__device__ float g_bmid[CB * SP];   // B_{512}[s],     natural s order (s>=201 -> NEGF)
__device__ float g_loss[CB];

// 3-way logsumexp in log2 domain, sort trick: 2 EX2 + 1 LG2.
__device__ __forceinline__ float lse3(float a, float b, float c)
{
    float mxab = fmaxf(a, b), mnab = fminf(a, b);
    float hi  = fmaxf(mxab, c);
    float mid = fmaxf(mnab, fminf(mxab, c));
    float lo  = fminf(mnab, c);
    return hi + __log2f(1.0f + exp2f(mid - hi) + exp2f(lo - hi));
}

// ---------------------------------------------------------------------------
// Kernel 1: per-(b,t) log-sum-exp over V fused with gather of extended-label
// log2-probs into the lane-permuted scratch layout.
// ---------------------------------------------------------------------------
__global__ void __launch_bounds__(256) lse_gather_kernel(
    const float* __restrict__ logits, const int* __restrict__ targets)
{
    const int t = blockIdx.x, b = blockIdx.y;
    const float* row = logits + ((size_t)b * CT + t) * CV;

    __shared__ float sh[CV];
    __shared__ float red[8];
    __shared__ float bc[2];

    const int tid = threadIdx.x;
    float4 v = reinterpret_cast<const float4*>(row)[tid];
    reinterpret_cast<float4*>(sh)[tid] = v;

    float m = fmaxf(fmaxf(v.x, v.y), fmaxf(v.z, v.w));
    #pragma unroll
    for (int o = 16; o > 0; o >>= 1) m = fmaxf(m, __shfl_xor_sync(0xffffffffu, m, o));
    if ((tid & 31) == 0) red[tid >> 5] = m;
    __syncthreads();
    if (tid < 8) {
        float mm = red[tid];
        #pragma unroll
        for (int o = 4; o > 0; o >>= 1) mm = fmaxf(mm, __shfl_xor_sync(0xffu, mm, o));
        if (tid == 0) bc[0] = mm;
    }
    __syncthreads();
    m = bc[0];

    float sum = exp2f((v.x - m) * LOG2E) + exp2f((v.y - m) * LOG2E)
              + exp2f((v.z - m) * LOG2E) + exp2f((v.w - m) * LOG2E);
    #pragma unroll
    for (int o = 16; o > 0; o >>= 1) sum += __shfl_xor_sync(0xffffffffu, sum, o);
    if ((tid & 31) == 0) red[tid >> 5] = sum;
    __syncthreads();
    if (tid < 8) {
        float ss = red[tid];
        #pragma unroll
        for (int o = 4; o > 0; o >>= 1) ss += __shfl_xor_sync(0xffu, ss, o);
        if (tid == 0) bc[1] = ss;
    }
    __syncthreads();

    const float lse2 = m * LOG2E + __log2f(bc[1]);   // log2(sum_v exp(x_v))

    if (tid < SP) {
        const int l = tid & 31, k = tid >> 5;
        const int s = NK * l + k;                    // extended state index
        float val = NEGF;
        if (s < CS) {
            int sym = (s & 1) ? targets[b * CL + (s >> 1)] : (CV - 1);
            val = sh[sym] * LOG2E - lse2;
        }
        g_lp[((size_t)b * CT + t) * SP + tid] = val;
    }
}

// ---------------------------------------------------------------------------
// Kernel 2: CTC DP, one warp per (batch, direction). No barriers, no SMEM.
// blockIdx.x < CB: forward (alpha_1..alpha_TMID); else backward (B_1022..B_513+1).
// Lane l owns states s = 7l..7l+6 in registers. Cross-lane halo via shfl.
// ---------------------------------------------------------------------------
__global__ void __launch_bounds__(32, 1) ctc_dp_kernel(const int* __restrict__ targets)
{
    const unsigned FULL = 0xffffffffu;
    const int cta = blockIdx.x;
    const bool bwd = (cta >= CB);
    const int b = bwd ? cta - CB : cta;
    const int l = threadIdx.x;
    const float* __restrict__ lpb = g_lp + (size_t)b * CT * SP + l;
    const int* __restrict__ tg = targets + b * CL;

    float a[NK];
    float lbuf[2][NK];

    if (!bwd) {
        // forward skip flags: state s, skip allowed iff s odd, s>=3, s<201, tg[s/2]!=tg[s/2-1]
        bool skip[NK];
        #pragma unroll
        for (int k = 0; k < NK; k++) {
            int s = NK * l + k;
            bool ok = (s & 1) && (s >= 3) && (s < CS);
            int i = min(s >> 1, CL - 1);
            int im = max(i - 1, 0);
            skip[k] = ok && (tg[i] != tg[im]);
        }
        // alpha_0
        #pragma unroll
        for (int k = 0; k < NK; k++) {
            int s = NK * l + k;
            float v = lpb[32 * k];                  // t = 0
            a[k] = (s < 2) ? v : NEGF;
        }
        // prefetch t=1 -> lbuf[1], t=2 -> lbuf[0]
        #pragma unroll
        for (int k = 0; k < NK; k++) {
            lbuf[1][k] = lpb[(size_t)1 * SP + 32 * k];
            lbuf[0][k] = lpb[(size_t)2 * SP + 32 * k];
        }
        #pragma unroll 2
        for (int t = 1; t <= TMID; t++) {
            float h1 = __shfl_up_sync(FULL, a[NK - 1], 1);
            float h2 = __shfl_up_sync(FULL, a[NK - 2], 1);
            if (l == 0) { h1 = NEGF; h2 = NEGF; }
            const float* lp = lbuf[t & 1];
            float n[NK];
            n[0] = lse3(a[0], h1,   skip[0] ? h2   : NEGF) + lp[0];
            n[1] = lse3(a[1], a[0], skip[1] ? h1   : NEGF) + lp[1];
            #pragma unroll
            for (int k = 2; k < NK; k++)
                n[k] = lse3(a[k], a[k - 1], skip[k] ? a[k - 2] : NEGF) + lp[k];
            // prefetch t+2
            if (t <= TMID - 2) {
                #pragma unroll
                for (int k = 0; k < NK; k++)
                    lbuf[t & 1][k] = lpb[(size_t)(t + 2) * SP + 32 * k];
            }
            #pragma unroll
            for (int k = 0; k < NK; k++) a[k] = n[k];
        }
        #pragma unroll
        for (int k = 0; k < NK; k++) {
            int s = NK * l + k;
            g_amid[b * SP + s] = (s < CS) ? a[k] : NEGF;
        }
    } else {
        // backward: B_t[s] = lp_t[s] + LSE(B_{t+1}[s], B_{t+1}[s+1], sd? B_{t+1}[s+2])
        // sd (dest-skip) for state s: d = s+2 odd, d<=200, tg[d/2]!=tg[d/2-1]
        bool sd[NK];
        #pragma unroll
        for (int k = 0; k < NK; k++) {
            int s = NK * l + k;
            int d = s + 2;
            bool ok = (d & 1) && (d < CS);
            int i = min(d >> 1, CL - 1);
            int im = max(i - 1, 0);
            sd[k] = ok && (tg[i] != tg[im]);
        }
        // B_{T-1}
        #pragma unroll
        for (int k = 0; k < NK; k++) {
            int s = NK * l + k;
            float v = lpb[(size_t)(CT - 1) * SP + 32 * k];
            a[k] = (s == CS - 1 || s == CS - 2) ? v : NEGF;
        }
        // prefetch t=1022 -> lbuf[0], t=1021 -> lbuf[1]
        #pragma unroll
        for (int k = 0; k < NK; k++) {
            lbuf[0][k] = lpb[(size_t)(CT - 2) * SP + 32 * k];
            lbuf[1][k] = lpb[(size_t)(CT - 3) * SP + 32 * k];
        }
        #pragma unroll 2
        for (int t = CT - 2; t >= TMID + 1; t--) {
            float h1 = __shfl_down_sync(FULL, a[0], 1);
            float h2 = __shfl_down_sync(FULL, a[1], 1);
            if (l == 31) { h1 = NEGF; h2 = NEGF; }
            const float* lp = lbuf[t & 1];
            float n[NK];
            #pragma unroll
            for (int k = 0; k < NK - 2; k++)
                n[k] = lse3(a[k], a[k + 1], sd[k] ? a[k + 2] : NEGF) + lp[k];
            n[NK - 2] = lse3(a[NK - 2], a[NK - 1], sd[NK - 2] ? h1 : NEGF) + lp[NK - 2];
            n[NK - 1] = lse3(a[NK - 1], h1,        sd[NK - 1] ? h2 : NEGF) + lp[NK - 1];
            if (t >= TMID + 3) {
                #pragma unroll
                for (int k = 0; k < NK; k++)
                    lbuf[t & 1][k] = lpb[(size_t)(t - 2) * SP + 32 * k];
            }
            #pragma unroll
            for (int k = 0; k < NK; k++) a[k] = n[k];
        }
        #pragma unroll
        for (int k = 0; k < NK; k++) {
            int s = NK * l + k;
            g_bmid[b * SP + s] = (s < CS) ? a[k] : NEGF;
        }
    }
}

// ---------------------------------------------------------------------------
// Kernel 3: combine. loss_b = -LSE_s( alpha_M[s] + beta_M[s] ),
// beta_M[s] = LSE(B_{M+1}[s], B_{M+1}[s+1], sd? B_{M+1}[s+2]).
// ---------------------------------------------------------------------------
__global__ void __launch_bounds__(256) combine_kernel(const int* __restrict__ targets)
{
    const int b = blockIdx.x, s = threadIdx.x;
    const int* __restrict__ tg = targets + b * CL;
    __shared__ float red[8];
    __shared__ float bc[2];

    float v = NEGF;
    if (s < CS) {
        float B0 = g_bmid[b * SP + s];
        float B1 = (s + 1 < SP) ? g_bmid[b * SP + s + 1] : NEGF;
        float B2 = (s + 2 < SP) ? g_bmid[b * SP + s + 2] : NEGF;
        int d = s + 2;
        bool ok = (d & 1) && (d < CS);
        int i = min(d >> 1, CL - 1);
        int im = max(i - 1, 0);
        bool sdv = ok && (tg[i] != tg[im]);
        float beta = lse3(B0, B1, sdv ? B2 : NEGF);
        v = g_amid[b * SP + s] + beta;
    }

    // block LSE reduce over 256 threads
    float m = v;
    #pragma unroll
    for (int o = 16; o > 0; o >>= 1) m = fmaxf(m, __shfl_xor_sync(0xffffffffu, m, o));
    if ((threadIdx.x & 31) == 0) red[threadIdx.x >> 5] = m;
    __syncthreads();
    if (threadIdx.x < 8) {
        float mm = red[threadIdx.x];
        #pragma unroll
        for (int o = 4; o > 0; o >>= 1) mm = fmaxf(mm, __shfl_xor_sync(0xffu, mm, o));
        if (threadIdx.x == 0) bc[0] = mm;
    }
    __syncthreads();
    m = bc[0];

    float sum = exp2f(v - m);
    #pragma unroll
    for (int o = 16; o > 0; o >>= 1) sum += __shfl_xor_sync(0xffffffffu, sum, o);
    if ((threadIdx.x & 31) == 0) red[threadIdx.x >> 5] = sum;
    __syncthreads();
    if (threadIdx.x < 8) {
        float ss = red[threadIdx.x];
        #pragma unroll
        for (int o = 4; o > 0; o >>= 1) ss += __shfl_xor_sync(0xffu, ss, o);
        if (threadIdx.x == 0) g_loss[b] = -(m + __log2f(ss)) * LN2F;
    }
}

// ---------------------------------------------------------------------------
// Kernel 4: deterministic serial mean over B.
// ---------------------------------------------------------------------------
__global__ void reduce_kernel(float* __restrict__ out)
{
    float sum = 0.0f;
    #pragma unroll
    for (int i = 0; i < CB; i++) sum += g_loss[i];
    out[0] = sum * (1.0f / CB);
}

extern "C" void kernel_launch(void* const* d_in, const int* in_sizes, int n_in,
                              void* d_out, int out_size)
{
    const int*   targets = (const int*)d_in[0];
    const float* logits  = (const float*)d_in[1];
    float*       out     = (float*)d_out;

    dim3 g1(CT, CB);
    lse_gather_kernel<<<g1, 256>>>(logits, targets);
    ctc_dp_kernel<<<2 * CB, 32>>>(targets);
    combine_kernel<<<CB, 256>>>(targets);
    reduce_kernel<<<1, 1>>>(out);
}

// round 9
// speedup vs baseline: 2.4764x; 1.0468x over previous
#include <cuda_runtime.h>

#define CB 32
#define CT 1024
#define CV 1024
#define CL 100
#define CS 201           // 2*L+1
#define SP 224           // 32 lanes * 7 states (permuted layout)
#define NK 7             // states per lane
#define TMID 511         // forward computes alpha_1..alpha_511; backward B_1022..B_512
#define NEGF (-1e30f)
#define LOG2E 1.4426950408889634f
#define LN2F  0.6931471805599453f
#define FULLM 0xffffffffu

// Scratch: gathered extended-label LOG2-probs, lane-permuted (R3-validated):
// [B][T][slot], slot = l + 32*k holds state s = 7*l + k. Slots with s>=201 hold NEGF.
__device__ float g_lp[(size_t)CB * CT * SP];
__device__ float g_amid[CB * SP];   // log2 alpha_{511}[s], natural order
__device__ float g_bmid[CB * SP];   // log2 B_{512}[s],     natural order
__device__ float g_loss[CB];

// 3-way logsumexp in log2 domain, sort trick: 2 EX2 + 1 LG2.
__device__ __forceinline__ float lse3(float a, float b, float c)
{
    float mxab = fmaxf(a, b), mnab = fminf(a, b);
    float hi  = fmaxf(mxab, c);
    float mid = fmaxf(mnab, fminf(mxab, c));
    float lo  = fminf(mnab, c);
    return hi + __log2f(1.0f + exp2f(mid - hi) + exp2f(lo - hi));
}

// ---------------------------------------------------------------------------
// Kernel 1: block softmax-LSE + gather (EXACT R3-passing code).
// grid = (T, B), 256 threads.
// ---------------------------------------------------------------------------
__global__ void __launch_bounds__(256) lse_gather_kernel(
    const float* __restrict__ logits, const int* __restrict__ targets)
{
    const int t = blockIdx.x, b = blockIdx.y;
    const float* row = logits + ((size_t)b * CT + t) * CV;

    __shared__ float sh[CV];
    __shared__ float red[8];
    __shared__ float bc[2];

    const int tid = threadIdx.x;
    float4 v = reinterpret_cast<const float4*>(row)[tid];
    reinterpret_cast<float4*>(sh)[tid] = v;

    float m = fmaxf(fmaxf(v.x, v.y), fmaxf(v.z, v.w));
    #pragma unroll
    for (int o = 16; o > 0; o >>= 1) m = fmaxf(m, __shfl_xor_sync(FULLM, m, o));
    if ((tid & 31) == 0) red[tid >> 5] = m;
    __syncthreads();
    if (tid < 8) {
        float mm = red[tid];
        #pragma unroll
        for (int o = 4; o > 0; o >>= 1) mm = fmaxf(mm, __shfl_xor_sync(0xffu, mm, o));
        if (tid == 0) bc[0] = mm;
    }
    __syncthreads();
    m = bc[0];

    float sum = exp2f((v.x - m) * LOG2E) + exp2f((v.y - m) * LOG2E)
              + exp2f((v.z - m) * LOG2E) + exp2f((v.w - m) * LOG2E);
    #pragma unroll
    for (int o = 16; o > 0; o >>= 1) sum += __shfl_xor_sync(FULLM, sum, o);
    if ((tid & 31) == 0) red[tid >> 5] = sum;
    __syncthreads();
    if (tid < 8) {
        float ss = red[tid];
        #pragma unroll
        for (int o = 4; o > 0; o >>= 1) ss += __shfl_xor_sync(0xffu, ss, o);
        if (tid == 0) bc[1] = ss;
    }
    __syncthreads();

    const float lse2 = m * LOG2E + __log2f(bc[1]);   // log2(sum_v exp(x_v))

    if (tid < SP) {
        const int l = tid & 31, k = tid >> 5;
        const int s = NK * l + k;                    // extended state index
        float val = NEGF;
        if (s < CS) {
            int sym = (s & 1) ? targets[b * CL + (s >> 1)] : (CV - 1);
            val = sh[sym] * LOG2E - lse2;            // log2 probability
        }
        g_lp[((size_t)b * CT + t) * SP + tid] = val;
    }
}

// ---------------------------------------------------------------------------
// Log-domain DP steps (EXACT R3 math), named-buffer operands only.
// ---------------------------------------------------------------------------
__device__ __forceinline__ void fwd_step(float a[NK], const float lp[NK],
                                         const bool sk[NK], int lane)
{
    float h1 = __shfl_up_sync(FULLM, a[NK - 1], 1);
    float h2 = __shfl_up_sync(FULLM, a[NK - 2], 1);
    if (lane == 0) { h1 = NEGF; h2 = NEGF; }
    float n[NK];
    n[0] = lse3(a[0], h1,   sk[0] ? h2   : NEGF) + lp[0];
    n[1] = lse3(a[1], a[0], sk[1] ? h1   : NEGF) + lp[1];
    #pragma unroll
    for (int k = 2; k < NK; k++)
        n[k] = lse3(a[k], a[k - 1], sk[k] ? a[k - 2] : NEGF) + lp[k];
    #pragma unroll
    for (int k = 0; k < NK; k++) a[k] = n[k];
}

__device__ __forceinline__ void bwd_step(float a[NK], const float lp[NK],
                                         const bool sd[NK], int lane)
{
    float h1 = __shfl_down_sync(FULLM, a[0], 1);
    float h2 = __shfl_down_sync(FULLM, a[1], 1);
    if (lane == 31) { h1 = NEGF; h2 = NEGF; }
    float n[NK];
    #pragma unroll
    for (int k = 0; k < NK - 2; k++)
        n[k] = lse3(a[k], a[k + 1], sd[k] ? a[k + 2] : NEGF) + lp[k];
    n[NK - 2] = lse3(a[NK - 2], a[NK - 1], sd[NK - 2] ? h1 : NEGF) + lp[NK - 2];
    n[NK - 1] = lse3(a[NK - 1], h1,        sd[NK - 1] ? h2 : NEGF) + lp[NK - 1];
    #pragma unroll
    for (int k = 0; k < NK; k++) a[k] = n[k];
}

// ---------------------------------------------------------------------------
// Kernel 2: CTC DP (log2 domain), one warp per (batch, direction).
// Identical math/ordering to the R3-passing kernel; the ONLY change is the
// prefetch ping-pong unrolled into two NAMED register buffers (no dynamic
// local-array indexing -> no local-memory spill).
// ---------------------------------------------------------------------------
__global__ void __launch_bounds__(32, 1) ctc_dp_kernel(const int* __restrict__ targets)
{
    const int cta = blockIdx.x;
    const bool bwd = (cta >= CB);
    const int b = bwd ? cta - CB : cta;
    const int l = threadIdx.x;
    const float* __restrict__ lpb = g_lp + (size_t)b * CT * SP + l;
    const int* __restrict__ tg = targets + b * CL;

    float a[NK], bufA[NK], bufB[NK];

    if (!bwd) {
        bool sk[NK];
        #pragma unroll
        for (int k = 0; k < NK; k++) {
            int s = NK * l + k;
            bool ok = (s & 1) && (s >= 3) && (s < CS);
            int i = min(s >> 1, CL - 1), im = max(i - 1, 0);
            sk[k] = ok && (tg[i] != tg[im]);
        }
        #pragma unroll
        for (int k = 0; k < NK; k++) {
            int s = NK * l + k;
            float v = lpb[32 * k];                    // t = 0
            a[k] = (s < 2) ? v : NEGF;
        }
        #pragma unroll
        for (int k = 0; k < NK; k++) {
            bufA[k] = lpb[(size_t)1 * SP + 32 * k];   // p_1
            bufB[k] = lpb[(size_t)2 * SP + 32 * k];   // p_2
        }
        #pragma unroll 1
        for (int t = 1; t <= TMID - 2; t += 2) {      // t = 1,3,...,509 -> steps 1..510
            fwd_step(a, bufA, sk, l);                 // step t
            #pragma unroll
            for (int k = 0; k < NK; k++) bufA[k] = lpb[(size_t)(t + 2) * SP + 32 * k];
            fwd_step(a, bufB, sk, l);                 // step t+1
            #pragma unroll
            for (int k = 0; k < NK; k++) bufB[k] = lpb[(size_t)(t + 3) * SP + 32 * k];
        }
        fwd_step(a, bufA, sk, l);                     // step 511 (bufA = p_511)
        #pragma unroll
        for (int k = 0; k < NK; k++) {
            int s = NK * l + k;
            g_amid[b * SP + s] = a[k];
        }
    } else {
        bool sd[NK];
        #pragma unroll
        for (int k = 0; k < NK; k++) {
            int s = NK * l + k;
            int d = s + 2;
            bool ok = (d & 1) && (d < CS);
            int i = min(d >> 1, CL - 1), im = max(i - 1, 0);
            sd[k] = ok && (tg[i] != tg[im]);
        }
        #pragma unroll
        for (int k = 0; k < NK; k++) {
            int s = NK * l + k;
            float v = lpb[(size_t)(CT - 1) * SP + 32 * k];
            a[k] = (s == CS - 1 || s == CS - 2) ? v : NEGF;
        }
        #pragma unroll
        for (int k = 0; k < NK; k++) {
            bufA[k] = lpb[(size_t)(CT - 2) * SP + 32 * k];  // p_1022
            bufB[k] = lpb[(size_t)(CT - 3) * SP + 32 * k];  // p_1021
        }
        #pragma unroll 1
        for (int t = CT - 2; t >= TMID + 3; t -= 2) { // t = 1022,1020,...,514 -> steps 1022..513
            bwd_step(a, bufA, sd, l);                 // step t
            #pragma unroll
            for (int k = 0; k < NK; k++) bufA[k] = lpb[(size_t)(t - 2) * SP + 32 * k];
            bwd_step(a, bufB, sd, l);                 // step t-1
            #pragma unroll
            for (int k = 0; k < NK; k++) bufB[k] = lpb[(size_t)(t - 3) * SP + 32 * k];
        }
        bwd_step(a, bufA, sd, l);                     // step 512 (bufA = p_512)
        #pragma unroll
        for (int k = 0; k < NK; k++) {
            int s = NK * l + k;
            g_bmid[b * SP + s] = a[k];
        }
    }
}

// ---------------------------------------------------------------------------
// Kernel 3: combine halves (log2 domain), per-batch block LSE reduce.
// (EXACT R3-passing code.)
// ---------------------------------------------------------------------------
__global__ void __launch_bounds__(256) combine_kernel(const int* __restrict__ targets)
{
    const int b = blockIdx.x, s = threadIdx.x;
    const int* __restrict__ tg = targets + b * CL;
    __shared__ float red[8];
    __shared__ float bc[2];

    float v = NEGF;
    if (s < CS) {
        float B0 = g_bmid[b * SP + s];
        float B1 = (s + 1 < SP) ? g_bmid[b * SP + s + 1] : NEGF;
        float B2 = (s + 2 < SP) ? g_bmid[b * SP + s + 2] : NEGF;
        int d = s + 2;
        bool ok = (d & 1) && (d < CS);
        int i = min(d >> 1, CL - 1), im = max(i - 1, 0);
        bool sdv = ok && (tg[i] != tg[im]);
        float beta = lse3(B0, B1, sdv ? B2 : NEGF);
        v = g_amid[b * SP + s] + beta;
    }

    float m = v;
    #pragma unroll
    for (int o = 16; o > 0; o >>= 1) m = fmaxf(m, __shfl_xor_sync(FULLM, m, o));
    if ((threadIdx.x & 31) == 0) red[threadIdx.x >> 5] = m;
    __syncthreads();
    if (threadIdx.x < 8) {
        float mm = red[threadIdx.x];
        #pragma unroll
        for (int o = 4; o > 0; o >>= 1) mm = fmaxf(mm, __shfl_xor_sync(0xffu, mm, o));
        if (threadIdx.x == 0) bc[0] = mm;
    }
    __syncthreads();
    m = bc[0];

    float sum = exp2f(v - m);
    #pragma unroll
    for (int o = 16; o > 0; o >>= 1) sum += __shfl_xor_sync(FULLM, sum, o);
    if ((threadIdx.x & 31) == 0) red[threadIdx.x >> 5] = sum;
    __syncthreads();
    if (threadIdx.x < 8) {
        float ss = red[threadIdx.x];
        #pragma unroll
        for (int o = 4; o > 0; o >>= 1) ss += __shfl_xor_sync(0xffu, ss, o);
        if (threadIdx.x == 0) g_loss[b] = -(m + __log2f(ss)) * LN2F;
    }
}

// ---------------------------------------------------------------------------
// Kernel 4: parallel mean over B (one warp).
// ---------------------------------------------------------------------------
__global__ void __launch_bounds__(32) reduce_kernel(float* __restrict__ out)
{
    float v = g_loss[threadIdx.x];
    #pragma unroll
    for (int o = 16; o > 0; o >>= 1) v += __shfl_xor_sync(FULLM, v, o);
    if (threadIdx.x == 0) out[0] = v * (1.0f / CB);
}

extern "C" void kernel_launch(void* const* d_in, const int* in_sizes, int n_in,
                              void* d_out, int out_size)
{
    const int*   targets = (const int*)d_in[0];
    const float* logits  = (const float*)d_in[1];
    float*       out     = (float*)d_out;

    dim3 g1(CT, CB);
    lse_gather_kernel<<<g1, 256>>>(logits, targets);
    ctc_dp_kernel<<<2 * CB, 32>>>(targets);
    combine_kernel<<<CB, 256>>>(targets);
    reduce_kernel<<<1, 32>>>(out);
}

// round 10
// speedup vs baseline: 3.1273x; 1.2628x over previous
#include <cuda_runtime.h>

#define CB 32
#define CT 1024
#define CV 1024
#define CL 100
#define CS 201           // 2*L+1
#define SP 224           // 32 lanes * 7 states (permuted layout)
#define NK 7             // states per lane
#define TMID 511
#define NEGF (-1e30f)
#define LOG2E 1.4426950408889634f
#define LN2F  0.6931471805599453f
#define FULLM 0xffffffffu

// Scratch: gathered extended-label LOG2-probs, lane-permuted:
// [B][T][slot], slot = l + 32*k holds state s = 7*l + k. Slots with s>=201 hold NEGF.
__device__ float g_lp[(size_t)CB * CT * SP];
__device__ float g_amid[CB * SP];   // log2 alpha_{511}[s]
__device__ float g_bmid[CB * SP];   // log2 B_{512}[s]

// 3-way logsumexp in log2 domain, sort trick: 2 EX2 + 1 LG2.
__device__ __forceinline__ float lse3(float a, float b, float c)
{
    float mxab = fmaxf(a, b), mnab = fminf(a, b);
    float hi  = fmaxf(mxab, c);
    float mid = fmaxf(mnab, fminf(mxab, c));
    float lo  = fminf(mnab, c);
    return hi + __log2f(1.0f + exp2f(mid - hi) + exp2f(lo - hi));
}

// ---------------------------------------------------------------------------
// Kernel 1: warp-per-row softmax-LSE + gather (log2 domain).
// grid = (CT/8, CB), 256 threads = 8 warps; warp w owns row t = bx*8 + w.
// No smem, no __syncthreads. Lane l computes states 7l+i -> coalesced stores.
// ---------------------------------------------------------------------------
__global__ void __launch_bounds__(256) lse_gather_kernel(
    const float* __restrict__ logits, const int* __restrict__ targets)
{
    const int lane = threadIdx.x & 31;
    const int w    = threadIdx.x >> 5;
    const int t    = blockIdx.x * 8 + w;
    const int b    = blockIdx.y;
    const float* __restrict__ row = logits + ((size_t)b * CT + t) * CV;
    const int* __restrict__ tg = targets + b * CL;

    const float4* r4 = reinterpret_cast<const float4*>(row);
    float4 v[8];
    #pragma unroll
    for (int i = 0; i < 8; i++) v[i] = r4[lane + 32 * i];

    // warp max
    float m = -3.4e38f;
    #pragma unroll
    for (int i = 0; i < 8; i++)
        m = fmaxf(m, fmaxf(fmaxf(v[i].x, v[i].y), fmaxf(v[i].z, v[i].w)));
    #pragma unroll
    for (int o = 16; o > 0; o >>= 1) m = fmaxf(m, __shfl_xor_sync(FULLM, m, o));

    // warp sum of 2^((x-m)*log2e)
    float s0 = 0.f, s1 = 0.f, s2 = 0.f, s3 = 0.f;
    #pragma unroll
    for (int i = 0; i < 8; i++) {
        s0 += exp2f((v[i].x - m) * LOG2E);
        s1 += exp2f((v[i].y - m) * LOG2E);
        s2 += exp2f((v[i].z - m) * LOG2E);
        s3 += exp2f((v[i].w - m) * LOG2E);
    }
    float sum = (s0 + s1) + (s2 + s3);
    #pragma unroll
    for (int o = 16; o > 0; o >>= 1) sum += __shfl_xor_sync(FULLM, sum, o);

    const float lse2 = m * LOG2E + __log2f(sum);     // log2(sum_v exp(x_v))

    // lane l emits states s = 7l + i into slot l + 32i  (coalesced stores)
    float* __restrict__ orow = g_lp + ((size_t)b * CT + t) * SP;
    #pragma unroll
    for (int i = 0; i < NK; i++) {
        const int s = NK * lane + i;
        float val = NEGF;
        if (s < CS) {
            int sym = (s & 1) ? __ldg(&tg[s >> 1]) : (CV - 1);
            val = __ldg(row + sym) * LOG2E - lse2;   // log2 probability
        }
        orow[lane + 32 * i] = val;
    }
}

// ---------------------------------------------------------------------------
// Log-domain DP steps (proven R9 math), named-buffer operands only.
// ---------------------------------------------------------------------------
__device__ __forceinline__ void fwd_step(float a[NK], const float lp[NK],
                                         const bool sk[NK], int lane)
{
    float h1 = __shfl_up_sync(FULLM, a[NK - 1], 1);
    float h2 = __shfl_up_sync(FULLM, a[NK - 2], 1);
    if (lane == 0) { h1 = NEGF; h2 = NEGF; }
    float n[NK];
    n[0] = lse3(a[0], h1,   sk[0] ? h2   : NEGF) + lp[0];
    n[1] = lse3(a[1], a[0], sk[1] ? h1   : NEGF) + lp[1];
    #pragma unroll
    for (int k = 2; k < NK; k++)
        n[k] = lse3(a[k], a[k - 1], sk[k] ? a[k - 2] : NEGF) + lp[k];
    #pragma unroll
    for (int k = 0; k < NK; k++) a[k] = n[k];
}

__device__ __forceinline__ void bwd_step(float a[NK], const float lp[NK],
                                         const bool sd[NK], int lane)
{
    float h1 = __shfl_down_sync(FULLM, a[0], 1);
    float h2 = __shfl_down_sync(FULLM, a[1], 1);
    if (lane == 31) { h1 = NEGF; h2 = NEGF; }
    float n[NK];
    #pragma unroll
    for (int k = 0; k < NK - 2; k++)
        n[k] = lse3(a[k], a[k + 1], sd[k] ? a[k + 2] : NEGF) + lp[k];
    n[NK - 2] = lse3(a[NK - 2], a[NK - 1], sd[NK - 2] ? h1 : NEGF) + lp[NK - 2];
    n[NK - 1] = lse3(a[NK - 1], h1,        sd[NK - 1] ? h2 : NEGF) + lp[NK - 1];
    #pragma unroll
    for (int k = 0; k < NK; k++) a[k] = n[k];
}

#define PF(buf, tt)                                                        \
    _Pragma("unroll")                                                      \
    for (int k = 0; k < NK; k++) buf[k] = lpb[(size_t)(tt) * SP + 32 * k];

// ---------------------------------------------------------------------------
// Kernel 2: CTC DP (log2 domain), one warp per (batch, direction).
// Identical math to R9; prefetch depth raised 2 -> 4 (named buffers A..D)
// to cover L2 latency (~262 cyc) with ~4 steps of slack.
// ---------------------------------------------------------------------------
__global__ void __launch_bounds__(32, 1) ctc_dp_kernel(const int* __restrict__ targets)
{
    const int cta = blockIdx.x;
    const bool bwd = (cta >= CB);
    const int b = bwd ? cta - CB : cta;
    const int l = threadIdx.x;
    const float* __restrict__ lpb = g_lp + (size_t)b * CT * SP + l;
    const int* __restrict__ tg = targets + b * CL;

    float a[NK], bufA[NK], bufB[NK], bufC[NK], bufD[NK];

    if (!bwd) {
        bool sk[NK];
        #pragma unroll
        for (int k = 0; k < NK; k++) {
            int s = NK * l + k;
            bool ok = (s & 1) && (s >= 3) && (s < CS);
            int i = min(s >> 1, CL - 1), im = max(i - 1, 0);
            sk[k] = ok && (tg[i] != tg[im]);
        }
        #pragma unroll
        for (int k = 0; k < NK; k++) {
            int s = NK * l + k;
            float v = lpb[32 * k];                    // t = 0
            a[k] = (s < 2) ? v : NEGF;
        }
        PF(bufA, 1) PF(bufB, 2) PF(bufC, 3) PF(bufD, 4)
        #pragma unroll 1
        for (int t = 1; t + 3 <= 508; t += 4) {       // steps 1..508
            fwd_step(a, bufA, sk, l);  PF(bufA, t + 4)
            fwd_step(a, bufB, sk, l);  PF(bufB, t + 5)
            fwd_step(a, bufC, sk, l);  PF(bufC, t + 6)
            fwd_step(a, bufD, sk, l);  PF(bufD, t + 7)
        }
        fwd_step(a, bufA, sk, l);                     // 509
        fwd_step(a, bufB, sk, l);                     // 510
        fwd_step(a, bufC, sk, l);                     // 511
        #pragma unroll
        for (int k = 0; k < NK; k++) {
            int s = NK * l + k;
            g_amid[b * SP + s] = (s < CS) ? a[k] : NEGF;
        }
    } else {
        bool sd[NK];
        #pragma unroll
        for (int k = 0; k < NK; k++) {
            int s = NK * l + k;
            int d = s + 2;
            bool ok = (d & 1) && (d < CS);
            int i = min(d >> 1, CL - 1), im = max(i - 1, 0);
            sd[k] = ok && (tg[i] != tg[im]);
        }
        #pragma unroll
        for (int k = 0; k < NK; k++) {
            int s = NK * l + k;
            float v = lpb[(size_t)(CT - 1) * SP + 32 * k];
            a[k] = (s == CS - 1 || s == CS - 2) ? v : NEGF;
        }
        PF(bufA, CT - 2) PF(bufB, CT - 3) PF(bufC, CT - 4) PF(bufD, CT - 5)
        #pragma unroll 1
        for (int t = CT - 2; t - 3 >= 515; t -= 4) {  // steps 1022..515
            bwd_step(a, bufA, sd, l);  PF(bufA, t - 4)
            bwd_step(a, bufB, sd, l);  PF(bufB, t - 5)
            bwd_step(a, bufC, sd, l);  PF(bufC, t - 6)
            bwd_step(a, bufD, sd, l);  PF(bufD, t - 7)
        }
        bwd_step(a, bufA, sd, l);                     // 514
        bwd_step(a, bufB, sd, l);                     // 513
        bwd_step(a, bufC, sd, l);                     // 512
        #pragma unroll
        for (int k = 0; k < NK; k++) {
            int s = NK * l + k;
            g_bmid[b * SP + s] = (s < CS) ? a[k] : NEGF;
        }
    }
}

// ---------------------------------------------------------------------------
// Kernel 3: fused combine + mean. One CTA, 1024 threads; warp b handles
// batch b (lane owns 7 states), then warp 0 averages the 32 losses.
// ---------------------------------------------------------------------------
__global__ void __launch_bounds__(1024) combine_reduce_kernel(
    const int* __restrict__ targets, float* __restrict__ out)
{
    const int b    = threadIdx.x >> 5;     // warp index = batch
    const int lane = threadIdx.x & 31;
    const int* __restrict__ tg = targets + b * CL;
    __shared__ float sloss[CB];

    float vk[NK];
    #pragma unroll
    for (int k = 0; k < NK; k++) {
        const int s = NK * lane + k;
        float v = NEGF;
        if (s < CS) {
            float B0 = g_bmid[b * SP + s];
            float B1 = g_bmid[b * SP + s + 1];
            float B2 = g_bmid[b * SP + s + 2];
            int d = s + 2;
            bool ok = (d & 1) && (d < CS);
            int i = min(d >> 1, CL - 1), im = max(i - 1, 0);
            bool sdv = ok && (tg[i] != tg[im]);
            float beta = lse3(B0, B1, sdv ? B2 : NEGF);
            v = g_amid[b * SP + s] + beta;
        }
        vk[k] = v;
    }

    float m = vk[0];
    #pragma unroll
    for (int k = 1; k < NK; k++) m = fmaxf(m, vk[k]);
    #pragma unroll
    for (int o = 16; o > 0; o >>= 1) m = fmaxf(m, __shfl_xor_sync(FULLM, m, o));

    float sum = 0.f;
    #pragma unroll
    for (int k = 0; k < NK; k++) sum += exp2f(vk[k] - m);
    #pragma unroll
    for (int o = 16; o > 0; o >>= 1) sum += __shfl_xor_sync(FULLM, sum, o);

    if (lane == 0) sloss[b] = -(m + __log2f(sum)) * LN2F;
    __syncthreads();

    if (threadIdx.x < 32) {
        float v = sloss[threadIdx.x];
        #pragma unroll
        for (int o = 16; o > 0; o >>= 1) v += __shfl_xor_sync(FULLM, v, o);
        if (threadIdx.x == 0) out[0] = v * (1.0f / CB);
    }
}

extern "C" void kernel_launch(void* const* d_in, const int* in_sizes, int n_in,
                              void* d_out, int out_size)
{
    const int*   targets = (const int*)d_in[0];
    const float* logits  = (const float*)d_in[1];
    float*       out     = (float*)d_out;

    dim3 g1(CT / 8, CB);
    lse_gather_kernel<<<g1, 256>>>(logits, targets);
    ctc_dp_kernel<<<2 * CB, 32>>>(targets);
    combine_reduce_kernel<<<1, 1024>>>(targets, out);
}

// round 12
// speedup vs baseline: 3.1637x; 1.0116x over previous
#include <cuda_runtime.h>

#define CB 32
#define CT 1024
#define CV 1024
#define CL 100
#define CS 201           // 2*L+1
#define SP 224           // 32 lanes * 7 states (permuted layout)
#define NK 7             // states per lane
#define TMID 511
#define NEGF (-1e30f)
#define LOG2E 1.4426950408889634f
#define LN2F  0.6931471805599453f
#define FULLM 0xffffffffu

// Scratch: gathered extended-label LOG2-probs, lane-permuted:
// [B][T][slot], slot = l + 32*k holds state s = 7*l + k. Slots with s>=201 hold NEGF.
__device__ float g_lp[(size_t)CB * CT * SP];
__device__ float g_amid[CB * SP];   // log2 alpha_{511}[s]
__device__ float g_bmid[CB * SP];   // log2 B_{512}[s]

// 3-way logsumexp in log2 domain (combine kernel only)
__device__ __forceinline__ float lse3(float a, float b, float c)
{
    float mxab = fmaxf(a, b), mnab = fminf(a, b);
    float hi  = fmaxf(mxab, c);
    float mid = fmaxf(mnab, fminf(mxab, c));
    float lo  = fminf(mnab, c);
    return hi + __log2f(1.0f + exp2f(mid - hi) + exp2f(lo - hi));
}

// ---------------------------------------------------------------------------
// Kernel 1: warp-per-row softmax-LSE + gather (log2 domain). Unchanged (R10).
// ---------------------------------------------------------------------------
__global__ void __launch_bounds__(256) lse_gather_kernel(
    const float* __restrict__ logits, const int* __restrict__ targets)
{
    const int lane = threadIdx.x & 31;
    const int w    = threadIdx.x >> 5;
    const int t    = blockIdx.x * 8 + w;
    const int b    = blockIdx.y;
    const float* __restrict__ row = logits + ((size_t)b * CT + t) * CV;
    const int* __restrict__ tg = targets + b * CL;

    const float4* r4 = reinterpret_cast<const float4*>(row);
    float4 v[8];
    #pragma unroll
    for (int i = 0; i < 8; i++) v[i] = r4[lane + 32 * i];

    float m = -3.4e38f;
    #pragma unroll
    for (int i = 0; i < 8; i++)
        m = fmaxf(m, fmaxf(fmaxf(v[i].x, v[i].y), fmaxf(v[i].z, v[i].w)));
    #pragma unroll
    for (int o = 16; o > 0; o >>= 1) m = fmaxf(m, __shfl_xor_sync(FULLM, m, o));

    float s0 = 0.f, s1 = 0.f, s2 = 0.f, s3 = 0.f;
    #pragma unroll
    for (int i = 0; i < 8; i++) {
        s0 += exp2f((v[i].x - m) * LOG2E);
        s1 += exp2f((v[i].y - m) * LOG2E);
        s2 += exp2f((v[i].z - m) * LOG2E);
        s3 += exp2f((v[i].w - m) * LOG2E);
    }
    float sum = (s0 + s1) + (s2 + s3);
    #pragma unroll
    for (int o = 16; o > 0; o >>= 1) sum += __shfl_xor_sync(FULLM, sum, o);

    const float lse2 = m * LOG2E + __log2f(sum);

    float* __restrict__ orow = g_lp + ((size_t)b * CT + t) * SP;
    #pragma unroll
    for (int i = 0; i < NK; i++) {
        const int s = NK * lane + i;
        float val = NEGF;
        if (s < CS) {
            int sym = (s & 1) ? __ldg(&tg[s >> 1]) : (CV - 1);
            val = __ldg(row + sym) * LOG2E - lse2;
        }
        orow[lane + 32 * i] = val;
    }
}

// ---------------------------------------------------------------------------
// STAGED log-domain DP steps: per-k arithmetic identical to R10's lse3 path,
// but emitted breadth-first across the 7 states so the 21 MUFU ops pipeline
// at issue rate instead of serializing 7 dependent chains.
// ---------------------------------------------------------------------------
__device__ __forceinline__ void fwd_step(float a[NK], const float lp[NK],
                                         const bool sk[NK], int lane)
{
    float h1 = __shfl_up_sync(FULLM, a[NK - 1], 1);
    float h2 = __shfl_up_sync(FULLM, a[NK - 2], 1);
    if (lane == 0) { h1 = NEGF; h2 = NEGF; }

    float x[NK], y[NK], z[NK];
    x[0] = a[0]; y[0] = h1;   z[0] = sk[0] ? h2 : NEGF;
    x[1] = a[1]; y[1] = a[0]; z[1] = sk[1] ? h1 : NEGF;
    #pragma unroll
    for (int k = 2; k < NK; k++) { x[k] = a[k]; y[k] = a[k - 1]; z[k] = sk[k] ? a[k - 2] : NEGF; }

    float hi[NK], mid[NK], lo[NK];
    #pragma unroll
    for (int k = 0; k < NK; k++) {
        float mx = fmaxf(x[k], y[k]), mn = fminf(x[k], y[k]);
        hi[k]  = fmaxf(mx, z[k]);
        mid[k] = fmaxf(mn, fminf(mx, z[k]));
        lo[k]  = fminf(mn, z[k]);
    }
    float e1[NK];
    #pragma unroll
    for (int k = 0; k < NK; k++) e1[k] = exp2f(mid[k] - hi[k]);
    float e2[NK];
    #pragma unroll
    for (int k = 0; k < NK; k++) e2[k] = exp2f(lo[k] - hi[k]);
    float lg[NK];
    #pragma unroll
    for (int k = 0; k < NK; k++) lg[k] = __log2f(1.0f + e1[k] + e2[k]);
    #pragma unroll
    for (int k = 0; k < NK; k++) a[k] = hi[k] + lg[k] + lp[k];
}

__device__ __forceinline__ void bwd_step(float a[NK], const float lp[NK],
                                         const bool sd[NK], int lane)
{
    float h1 = __shfl_down_sync(FULLM, a[0], 1);
    float h2 = __shfl_down_sync(FULLM, a[1], 1);
    if (lane == 31) { h1 = NEGF; h2 = NEGF; }

    float x[NK], y[NK], z[NK];
    #pragma unroll
    for (int k = 0; k < NK - 2; k++) { x[k] = a[k]; y[k] = a[k + 1]; z[k] = sd[k] ? a[k + 2] : NEGF; }
    x[NK - 2] = a[NK - 2]; y[NK - 2] = a[NK - 1]; z[NK - 2] = sd[NK - 2] ? h1 : NEGF;
    x[NK - 1] = a[NK - 1]; y[NK - 1] = h1;        z[NK - 1] = sd[NK - 1] ? h2 : NEGF;

    float hi[NK], mid[NK], lo[NK];
    #pragma unroll
    for (int k = 0; k < NK; k++) {
        float mx = fmaxf(x[k], y[k]), mn = fminf(x[k], y[k]);
        hi[k]  = fmaxf(mx, z[k]);
        mid[k] = fmaxf(mn, fminf(mx, z[k]));
        lo[k]  = fminf(mn, z[k]);
    }
    float e1[NK];
    #pragma unroll
    for (int k = 0; k < NK; k++) e1[k] = exp2f(mid[k] - hi[k]);
    float e2[NK];
    #pragma unroll
    for (int k = 0; k < NK; k++) e2[k] = exp2f(lo[k] - hi[k]);
    float lg[NK];
    #pragma unroll
    for (int k = 0; k < NK; k++) lg[k] = __log2f(1.0f + e1[k] + e2[k]);
    #pragma unroll
    for (int k = 0; k < NK; k++) a[k] = hi[k] + lg[k] + lp[k];
}

#define PF(buf, tt)                                                        \
    _Pragma("unroll")                                                      \
    for (int k = 0; k < NK; k++) buf[k] = lpb[(size_t)(tt) * SP + 32 * k];

// ---------------------------------------------------------------------------
// Kernel 2: CTC DP (log2 domain), one warp per (batch, direction).
// Loop/buffer structure identical to R10 (validated); only step internals
// restructured for ILP.
// ---------------------------------------------------------------------------
__global__ void __launch_bounds__(32, 1) ctc_dp_kernel(const int* __restrict__ targets)
{
    const int cta = blockIdx.x;
    const bool bwd = (cta >= CB);
    const int b = bwd ? cta - CB : cta;
    const int l = threadIdx.x;
    const float* __restrict__ lpb = g_lp + (size_t)b * CT * SP + l;
    const int* __restrict__ tg = targets + b * CL;

    float a[NK], bufA[NK], bufB[NK], bufC[NK], bufD[NK];

    if (!bwd) {
        bool sk[NK];
        #pragma unroll
        for (int k = 0; k < NK; k++) {
            int s = NK * l + k;
            bool ok = (s & 1) && (s >= 3) && (s < CS);
            int i = min(s >> 1, CL - 1), im = max(i - 1, 0);
            sk[k] = ok && (tg[i] != tg[im]);
        }
        #pragma unroll
        for (int k = 0; k < NK; k++) {
            int s = NK * l + k;
            float v = lpb[32 * k];                    // t = 0
            a[k] = (s < 2) ? v : NEGF;
        }
        PF(bufA, 1) PF(bufB, 2) PF(bufC, 3) PF(bufD, 4)
        #pragma unroll 1
        for (int t = 1; t + 3 <= 508; t += 4) {       // steps 1..508
            fwd_step(a, bufA, sk, l);  PF(bufA, t + 4)
            fwd_step(a, bufB, sk, l);  PF(bufB, t + 5)
            fwd_step(a, bufC, sk, l);  PF(bufC, t + 6)
            fwd_step(a, bufD, sk, l);  PF(bufD, t + 7)
        }
        fwd_step(a, bufA, sk, l);                     // 509
        fwd_step(a, bufB, sk, l);                     // 510
        fwd_step(a, bufC, sk, l);                     // 511
        #pragma unroll
        for (int k = 0; k < NK; k++) {
            int s = NK * l + k;
            g_amid[b * SP + s] = (s < CS) ? a[k] : NEGF;
        }
    } else {
        bool sd[NK];
        #pragma unroll
        for (int k = 0; k < NK; k++) {
            int s = NK * l + k;
            int d = s + 2;
            bool ok = (d & 1) && (d < CS);
            int i = min(d >> 1, CL - 1), im = max(i - 1, 0);
            sd[k] = ok && (tg[i] != tg[im]);
        }
        #pragma unroll
        for (int k = 0; k < NK; k++) {
            int s = NK * l + k;
            float v = lpb[(size_t)(CT - 1) * SP + 32 * k];
            a[k] = (s == CS - 1 || s == CS - 2) ? v : NEGF;
        }
        PF(bufA, CT - 2) PF(bufB, CT - 3) PF(bufC, CT - 4) PF(bufD, CT - 5)
        #pragma unroll 1
        for (int t = CT - 2; t - 3 >= 515; t -= 4) {  // steps 1022..515
            bwd_step(a, bufA, sd, l);  PF(bufA, t - 4)
            bwd_step(a, bufB, sd, l);  PF(bufB, t - 5)
            bwd_step(a, bufC, sd, l);  PF(bufC, t - 6)
            bwd_step(a, bufD, sd, l);  PF(bufD, t - 7)
        }
        bwd_step(a, bufA, sd, l);                     // 514
        bwd_step(a, bufB, sd, l);                     // 513
        bwd_step(a, bufC, sd, l);                     // 512
        #pragma unroll
        for (int k = 0; k < NK; k++) {
            int s = NK * l + k;
            g_bmid[b * SP + s] = (s < CS) ? a[k] : NEGF;
        }
    }
}

// ---------------------------------------------------------------------------
// Kernel 3: fused combine + mean. Unchanged (R10).
// ---------------------------------------------------------------------------
__global__ void __launch_bounds__(1024) combine_reduce_kernel(
    const int* __restrict__ targets, float* __restrict__ out)
{
    const int b    = threadIdx.x >> 5;     // warp index = batch
    const int lane = threadIdx.x & 31;
    const int* __restrict__ tg = targets + b * CL;
    __shared__ float sloss[CB];

    float vk[NK];
    #pragma unroll
    for (int k = 0; k < NK; k++) {
        const int s = NK * lane + k;
        float v = NEGF;
        if (s < CS) {
            float B0 = g_bmid[b * SP + s];
            float B1 = g_bmid[b * SP + s + 1];
            float B2 = g_bmid[b * SP + s + 2];
            int d = s + 2;
            bool ok = (d & 1) && (d < CS);
            int i = min(d >> 1, CL - 1), im = max(i - 1, 0);
            bool sdv = ok && (tg[i] != tg[im]);
            float beta = lse3(B0, B1, sdv ? B2 : NEGF);
            v = g_amid[b * SP + s] + beta;
        }
        vk[k] = v;
    }

    float m = vk[0];
    #pragma unroll
    for (int k = 1; k < NK; k++) m = fmaxf(m, vk[k]);
    #pragma unroll
    for (int o = 16; o > 0; o >>= 1) m = fmaxf(m, __shfl_xor_sync(FULLM, m, o));

    float sum = 0.f;
    #pragma unroll
    for (int k = 0; k < NK; k++) sum += exp2f(vk[k] - m);
    #pragma unroll
    for (int o = 16; o > 0; o >>= 1) sum += __shfl_xor_sync(FULLM, sum, o);

    if (lane == 0) sloss[b] = -(m + __log2f(sum)) * LN2F;
    __syncthreads();

    if (threadIdx.x < 32) {
        float v = sloss[threadIdx.x];
        #pragma unroll
        for (int o = 16; o > 0; o >>= 1) v += __shfl_xor_sync(FULLM, v, o);
        if (threadIdx.x == 0) out[0] = v * (1.0f / CB);
    }
}

extern "C" void kernel_launch(void* const* d_in, const int* in_sizes, int n_in,
                              void* d_out, int out_size)
{
    const int*   targets = (const int*)d_in[0];
    const float* logits  = (const float*)d_in[1];
    float*       out     = (float*)d_out;

    dim3 g1(CT / 8, CB);
    lse_gather_kernel<<<g1, 256>>>(logits, targets);
    ctc_dp_kernel<<<2 * CB, 32>>>(targets);
    combine_reduce_kernel<<<1, 1024>>>(targets, out);
}

// round 16
// speedup vs baseline: 3.3734x; 1.0663x over previous
#include <cuda_runtime.h>

#define CB 32
#define CT 1024
#define CV 1024
#define CL 100
#define CS 201           // 2*L+1
#define SP 224           // 32 lanes * 7 states (permuted layout)
#define NK 7             // states per lane
#define LOG2E 1.4426950408889634f
#define LN2F  0.6931471805599453f
#define FULLM 0xffffffffu

// Scratch: softmax PROBABILITIES of extended labels, lane-permuted
// (validated layout): [B][T][slot], slot = l + 32*k holds state s = 7*l + k.
// Slots with s >= 201 hold 0.
__device__ float g_lp[(size_t)CB * CT * SP];
__device__ float g_loss[CB];

// ---------------------------------------------------------------------------
// Kernel 1: warp-per-row softmax + gather of extended-label PROBABILITIES.
// (Unchanged from R15 — validated.)
// ---------------------------------------------------------------------------
__global__ void __launch_bounds__(256) prob_gather_kernel(
    const float* __restrict__ logits, const int* __restrict__ targets)
{
    const int lane = threadIdx.x & 31;
    const int w    = threadIdx.x >> 5;
    const int t    = blockIdx.x * 8 + w;
    const int b    = blockIdx.y;
    const float* __restrict__ row = logits + ((size_t)b * CT + t) * CV;
    const int* __restrict__ tg = targets + b * CL;

    const float4* r4 = reinterpret_cast<const float4*>(row);
    float4 v[8];
    #pragma unroll
    for (int i = 0; i < 8; i++) v[i] = r4[lane + 32 * i];

    float m = -3.4e38f;
    #pragma unroll
    for (int i = 0; i < 8; i++)
        m = fmaxf(m, fmaxf(fmaxf(v[i].x, v[i].y), fmaxf(v[i].z, v[i].w)));
    #pragma unroll
    for (int o = 16; o > 0; o >>= 1) m = fmaxf(m, __shfl_xor_sync(FULLM, m, o));

    float s0 = 0.f, s1 = 0.f, s2 = 0.f, s3 = 0.f;
    #pragma unroll
    for (int i = 0; i < 8; i++) {
        s0 += exp2f((v[i].x - m) * LOG2E);
        s1 += exp2f((v[i].y - m) * LOG2E);
        s2 += exp2f((v[i].z - m) * LOG2E);
        s3 += exp2f((v[i].w - m) * LOG2E);
    }
    float sum = (s0 + s1) + (s2 + s3);
    #pragma unroll
    for (int o = 16; o > 0; o >>= 1) sum += __shfl_xor_sync(FULLM, sum, o);

    const float lse2 = m * LOG2E + __log2f(sum);     // log2(sum_v exp(x_v))

    float* __restrict__ orow = g_lp + ((size_t)b * CT + t) * SP;
    #pragma unroll
    for (int i = 0; i < NK; i++) {
        const int s = NK * lane + i;
        float val = 0.0f;
        if (s < CS) {
            int sym = (s & 1) ? __ldg(&tg[s >> 1]) : (CV - 1);
            val = exp2f(__ldg(row + sym) * LOG2E - lse2);   // probability
        }
        orow[lane + 32 * i] = val;
    }
}

// ---------------------------------------------------------------------------
// Probability-domain forward step with per-lane scale correction on the halo.
// hs1*hs2 = 2^(D_self - D_{lane-1}) (exact powers of 2, pre-split).
// ---------------------------------------------------------------------------
__device__ __forceinline__ void prob_step(float a[NK], const float p[NK],
                                          const bool sk[NK], int lane,
                                          float hs1, float hs2)
{
    float h1 = __shfl_up_sync(FULLM, a[NK - 1], 1);
    float h2 = __shfl_up_sync(FULLM, a[NK - 2], 1);
    h1 = (h1 * hs1) * hs2;
    h2 = (h2 * hs1) * hs2;
    if (lane == 0) { h1 = 0.f; h2 = 0.f; }
    float n[NK];
    n[0] = (a[0] + h1   + (sk[0] ? h2   : 0.f)) * p[0];
    n[1] = (a[1] + a[0] + (sk[1] ? h1   : 0.f)) * p[1];
    #pragma unroll
    for (int k = 2; k < NK; k++)
        n[k] = (a[k] + a[k - 1] + (sk[k] ? a[k - 2] : 0.f)) * p[k];
    #pragma unroll
    for (int k = 0; k < NK; k++) a[k] = n[k];
}

// ---------------------------------------------------------------------------
// PER-LANE exact power-of-2 renormalization (targets lane max ~ 2^20).
// All-zero lanes adopt the lower neighbor's scale so the activation front
// enters at the correct magnitude. Recomputes the halo correction factors.
// ---------------------------------------------------------------------------
__device__ __forceinline__ void renorm_lane(float a[NK], int& D,
                                            float& hs1, float& hs2)
{
    float m = fmaxf(fmaxf(fmaxf(a[0], a[1]), fmaxf(a[2], a[3])),
                    fmaxf(fmaxf(a[4], a[5]), a[6]));
    const bool z = (m == 0.0f);
    int e  = (int)(__float_as_uint(m) >> 23);
    int sf = z ? 127 : min(max(274 - e, 1), 254);    // lane max -> exponent 147
    float sc = __uint_as_float((unsigned)sf << 23);
    #pragma unroll
    for (int k = 0; k < NK; k++) a[k] *= sc;

    int Dn = D + (sf - 127);
    int Dup = __shfl_up_sync(FULLM, Dn, 1);          // neighbor's pre-adoption Dn
    if (z) Dn = Dup;                                 // adopt scale while inactive
    D = Dn;

    int Dup2 = __shfl_up_sync(FULLM, Dn, 1);         // neighbor's final D
    int d = Dn - Dup2;                               // halo: lane-1 frame -> own frame
    d = min(max(d, -252), 252);
    int d1 = d >> 1;                                 // floor halves, both in [-126,127]
    int d2 = d - d1;
    hs1 = __uint_as_float((unsigned)(127 + d1) << 23);
    hs2 = __uint_as_float((unsigned)(127 + d2) << 23);
}

#define PF(buf, tt)                                                        \
    _Pragma("unroll")                                                      \
    for (int k = 0; k < NK; k++) buf[k] = lpb[(size_t)(tt) * SP + 32 * k];

// ---------------------------------------------------------------------------
// Kernel 2: forward-only CTC DP over the full sequence (1023 steps).
// One warp per batch; per-lane scaling. Loop structure unchanged (R15).
// ---------------------------------------------------------------------------
__global__ void __launch_bounds__(32, 1) ctc_dp_kernel(const int* __restrict__ targets)
{
    const int b = blockIdx.x;
    const int l = threadIdx.x;
    const float* __restrict__ lpb = g_lp + (size_t)b * CT * SP + l;
    const int* __restrict__ tg = targets + b * CL;

    bool sk[NK];
    #pragma unroll
    for (int k = 0; k < NK; k++) {
        int s = NK * l + k;
        bool ok = (s & 1) && (s >= 3) && (s < CS);
        int i = min(s >> 1, CL - 1), im = max((s >> 1) - 1, 0);
        sk[k] = ok && (__ldg(&tg[i]) != __ldg(&tg[im]));
    }

    float a[NK], bufA[NK], bufB[NK], bufC[NK], bufD[NK];
    int D = 0;
    float hs1 = 1.0f, hs2 = 1.0f;

    #pragma unroll
    for (int k = 0; k < NK; k++) {
        int s = NK * l + k;
        float v = lpb[32 * k];                        // t = 0
        a[k] = (s < 2) ? v : 0.f;
    }
    PF(bufA, 1) PF(bufB, 2) PF(bufC, 3) PF(bufD, 4)

    #pragma unroll 1
    for (int t = 1; t + 3 <= CT - 4; t += 4) {        // steps 1..1020
        prob_step(a, bufA, sk, l, hs1, hs2);  PF(bufA, t + 4)
        prob_step(a, bufB, sk, l, hs1, hs2);  PF(bufB, t + 5)
        prob_step(a, bufC, sk, l, hs1, hs2);  PF(bufC, t + 6)
        prob_step(a, bufD, sk, l, hs1, hs2);  PF(bufD, (t + 7 < CT) ? (t + 7) : (CT - 1))
        renorm_lane(a, D, hs1, hs2);                  // every 4 steps
    }
    prob_step(a, bufA, sk, l, hs1, hs2);              // step 1021
    prob_step(a, bufB, sk, l, hs1, hs2);              // step 1022
    prob_step(a, bufC, sk, l, hs1, hs2);              // step 1023

    // loss_b = -ln(alpha[199] + alpha[200]); both live in lane 28 (k=3,4),
    // same per-lane scale D.
    if (l == 28) {
        float r = a[3] + a[4];
        g_loss[b] = -(__log2f(r) - (float)D) * LN2F;
    }
}

// ---------------------------------------------------------------------------
// Kernel 3: mean over B (one warp).
// ---------------------------------------------------------------------------
__global__ void __launch_bounds__(32) reduce_kernel(float* __restrict__ out)
{
    float v = g_loss[threadIdx.x];
    #pragma unroll
    for (int o = 16; o > 0; o >>= 1) v += __shfl_xor_sync(FULLM, v, o);
    if (threadIdx.x == 0) out[0] = v * (1.0f / CB);
}

extern "C" void kernel_launch(void* const* d_in, const int* in_sizes, int n_in,
                              void* d_out, int out_size)
{
    const int*   targets = (const int*)d_in[0];
    const float* logits  = (const float*)d_in[1];
    float*       out     = (float*)d_out;

    dim3 g1(CT / 8, CB);
    prob_gather_kernel<<<g1, 256>>>(logits, targets);
    ctc_dp_kernel<<<CB, 32>>>(targets);
    reduce_kernel<<<1, 32>>>(out);
}